// round 5
// baseline (speedup 1.0000x reference)
#include <cuda_runtime.h>
#include <cuda_fp16.h>
#include <cstdint>

// ============================================================================
// Sizes
// ============================================================================
#define MDIM 16384
#define NDIM 2048
#define KDIM 2048

#define BM 128
#define BN 128
#define BK 32
#define NK (KDIM / BK)            // 64 k-chunks
#define STAGES 2
#define NTILES (NDIM / BN)        // 16
#define MTILES (MDIM / BM)        // 128
#define GRID_CTAS (MTILES * NTILES)

// Static SMEM: per stage, A tile 128 rows x 32 halfs padded to 40 halfs (80B)
// = 10240B, B tile same. Stage stride 20480B. 2 stages = 40960B <= 48KB static,
// so NO cudaFuncSetAttribute is needed anywhere.
#define ROW_PITCH 80
#define TILE_BYTES 10240
#define STAGE_BYTES 20480
#define SMEM_TOTAL (STAGES * STAGE_BYTES)

// ============================================================================
// Static scratch (sanctioned no-alloc path)
// ============================================================================
__device__ __align__(256) __half g_xh[(size_t)MDIM * KDIM];   // 64 MB
__device__ __align__(256) __half g_wh[(size_t)NDIM * KDIM];   // 8 MB

// ============================================================================
// Helpers
// ============================================================================
__device__ __forceinline__ uint32_t smem_u32(const void* p) {
    uint32_t a;
    asm("{ .reg .u64 t; cvta.to.shared.u64 t, %1; cvt.u32.u64 %0, t; }" : "=r"(a) : "l"(p));
    return a;
}

__device__ __forceinline__ void cp_async16(uint32_t dst_smem, const void* src) {
    asm volatile("cp.async.cg.shared.global [%0], [%1], 16;" :: "r"(dst_smem), "l"(src) : "memory");
}
#define CP_COMMIT() asm volatile("cp.async.commit_group;" ::: "memory")
#define CP_WAIT(n)  asm volatile("cp.async.wait_group %0;" :: "n"(n) : "memory")

__device__ __forceinline__ void mma16816(float* d, const uint32_t* a, const uint32_t* b) {
    asm volatile(
        "mma.sync.aligned.m16n8k16.row.col.f32.f16.f16.f32 "
        "{%0,%1,%2,%3}, {%4,%5,%6,%7}, {%8,%9}, {%0,%1,%2,%3};"
        : "+f"(d[0]), "+f"(d[1]), "+f"(d[2]), "+f"(d[3])
        : "r"(a[0]), "r"(a[1]), "r"(a[2]), "r"(a[3]), "r"(b[0]), "r"(b[1]));
}

// ============================================================================
// Phase 1a: W_eff = weight + sum_r kron(L0_r,L1_r,L2_r)[:2048,:2048]  -> fp16
// ============================================================================
__global__ void __launch_bounds__(256) prep_w_kernel(const float* __restrict__ weight,
                                                     const float* __restrict__ leaf) {
    int idx = blockIdx.x * 256 + threadIdx.x;   // exactly NDIM*KDIM threads
    int n = idx >> 11;
    int k = idx & 2047;
    int n1 = n / 169; int nr = n - n1 * 169; int n2 = nr / 13; int n3 = nr - n2 * 13;
    int k1 = k / 169; int kr = k - k1 * 169; int k2 = kr / 13; int k3 = kr - k2 * 13;
    float d = 0.f;
#pragma unroll
    for (int r = 0; r < 4; r++) {
        float a = __ldg(&leaf[((0 * 4 + r) * 13 + n1) * 13 + k1]);
        float b = __ldg(&leaf[((1 * 4 + r) * 13 + n2) * 13 + k2]);
        float c = __ldg(&leaf[((2 * 4 + r) * 13 + n3) * 13 + k3]);
        d += a * b * c;
    }
    g_wh[idx] = __float2half(weight[idx] + d);
}

// ============================================================================
// Phase 1b: x fp32 -> fp16
// ============================================================================
__global__ void __launch_bounds__(256) convert_x_kernel(const float4* __restrict__ x) {
    size_t i = (size_t)blockIdx.x * 256 + threadIdx.x;   // M*K/4 threads
    float4 v = x[i];
    __half2 h0 = __floats2half2_rn(v.x, v.y);
    __half2 h1 = __floats2half2_rn(v.z, v.w);
    __half2* p = reinterpret_cast<__half2*>(g_xh);
    p[2 * i] = h0;
    p[2 * i + 1] = h1;
}

// ============================================================================
// Phase 2: GEMM  y = x @ W_eff^T + bias   (fp16 HMMA, fp32 accum)
// CTA 128x128, 8 warps (2x4), warp tile 64x32, BK=32, 2-stage cp.async,
// STATIC shared memory (no attribute calls).
// ============================================================================
__global__ void __launch_bounds__(256, 2)
gemm_kernel(const float* __restrict__ bias, float* __restrict__ out)
{
    __shared__ __align__(16) char smem[SMEM_TOTAL];
    const uint32_t sb = smem_u32(smem);
    const int tid = threadIdx.x;
    const int lane = tid & 31;
    const int wid = tid >> 5;
    const int wm = wid >> 2;           // 0..1  (64-row half)
    const int wn = wid & 3;            // 0..3  (32-col quarter)
    const int r1 = lane >> 2;          // 0..7
    const int c0 = (lane & 3) * 2;     // 0,2,4,6

    const int ntile = (int)blockIdx.x & (NTILES - 1);
    const int mtile = (int)blockIdx.x >> 4;
    const int m0 = mtile * BM;
    const int n0 = ntile * BN;

    const __half* gA = g_xh + (size_t)m0 * KDIM;
    const __half* gB = g_wh + (size_t)n0 * KDIM;

    // ---- async stage loader: 512 16B chunks A + 512 B, 4 per thread ----
    auto load_stage = [&](int kc, int s) {
        uint32_t sa = sb + s * STAGE_BYTES;
        uint32_t sB = sa + TILE_BYTES;
        int koff = kc * BK;
#pragma unroll
        for (int i = 0; i < 2; i++) {
            int c = tid + 256 * i;           // 0..511
            int row = c >> 2;                // 0..127
            int k8 = c & 3;                  // 16B chunk within 64B row payload
            cp_async16(sa + row * ROW_PITCH + k8 * 16, gA + (size_t)row * KDIM + koff + k8 * 8);
            cp_async16(sB + row * ROW_PITCH + k8 * 16, gB + (size_t)row * KDIM + koff + k8 * 8);
        }
        CP_COMMIT();
    };

    float acc[4][4][4];
#pragma unroll
    for (int i = 0; i < 4; i++)
#pragma unroll
        for (int j = 0; j < 4; j++)
#pragma unroll
            for (int q = 0; q < 4; q++) acc[i][j][q] = 0.f;

    load_stage(0, 0);   // prologue

    for (int kc = 0; kc < NK; kc++) {
        // issue next stage's loads (into the buffer freed by the trailing
        // __syncthreads of the previous iteration)
        if (kc + 1 < NK) {
            load_stage(kc + 1, (kc + 1) & 1);
            CP_WAIT(1);          // stage kc complete (kc+1 still in flight)
        } else {
            CP_WAIT(0);          // final stage complete
        }
        __syncthreads();

        const char* sa = smem + (kc & 1) * STAGE_BYTES;
        const char* sB = sa + TILE_BYTES;

#pragma unroll
        for (int kk = 0; kk < BK; kk += 16) {
            uint32_t a[4][4];
            uint32_t b[4][2];
#pragma unroll
            for (int ma = 0; ma < 4; ma++) {
                const char* base = sa + (wm * 64 + ma * 16 + r1) * ROW_PITCH + (kk + c0) * 2;
                a[ma][0] = *(const uint32_t*)(base);
                a[ma][1] = *(const uint32_t*)(base + 8 * ROW_PITCH);
                a[ma][2] = *(const uint32_t*)(base + 16);
                a[ma][3] = *(const uint32_t*)(base + 8 * ROW_PITCH + 16);
            }
#pragma unroll
            for (int nb = 0; nb < 4; nb++) {
                const char* base = sB + (wn * 32 + nb * 8 + r1) * ROW_PITCH + (kk + c0) * 2;
                b[nb][0] = *(const uint32_t*)(base);
                b[nb][1] = *(const uint32_t*)(base + 16);
            }
#pragma unroll
            for (int ma = 0; ma < 4; ma++)
#pragma unroll
                for (int nb = 0; nb < 4; nb++)
                    mma16816(acc[ma][nb], a[ma], b[nb]);
        }
        __syncthreads();   // all warps done with buffer kc&1 before it is refilled
    }

    // ---- epilogue: + bias, fp32 out ----
#pragma unroll
    for (int ma = 0; ma < 4; ma++) {
        int row0 = m0 + wm * 64 + ma * 16 + r1;
        float* orow0 = out + (size_t)row0 * NDIM;
        float* orow1 = orow0 + (size_t)8 * NDIM;
#pragma unroll
        for (int nb = 0; nb < 4; nb++) {
            int col = n0 + wn * 32 + nb * 8 + c0;
            float bv0 = __ldg(&bias[col]);
            float bv1 = __ldg(&bias[col + 1]);
            float2 v0 = make_float2(acc[ma][nb][0] + bv0, acc[ma][nb][1] + bv1);
            float2 v1 = make_float2(acc[ma][nb][2] + bv0, acc[ma][nb][3] + bv1);
            *reinterpret_cast<float2*>(orow0 + col) = v0;
            *reinterpret_cast<float2*>(orow1 + col) = v1;
        }
    }
}

// ============================================================================
// Host: kernel launches only -- no attribute calls, no allocation, no sync.
// ============================================================================
extern "C" void kernel_launch(void* const* d_in, const int* in_sizes, int n_in,
                              void* d_out, int out_size) {
    // Identify inputs by element count (robust to metadata ordering).
    const float* x = nullptr;
    const float* leaf = nullptr;
    const float* weight = nullptr;
    const float* bias = nullptr;
    for (int i = 0; i < n_in; i++) {
        switch (in_sizes[i]) {
            case 2028:     leaf   = (const float*)d_in[i]; break;  // 3*4*13*13
            case 2048:     bias   = (const float*)d_in[i]; break;
            case 4194304:  weight = (const float*)d_in[i]; break;  // 2048*2048
            default:       x      = (const float*)d_in[i]; break;  // 8*2048*2048
        }
    }
    float* out = (float*)d_out;

    prep_w_kernel<<<(NDIM * KDIM) / 256, 256>>>(weight, leaf);
    convert_x_kernel<<<(int)(((size_t)MDIM * KDIM / 4) / 256), 256>>>((const float4*)x);
    gemm_kernel<<<GRID_CTAS, 256>>>(bias, out);
}

// round 6
// speedup vs baseline: 1.1084x; 1.1084x over previous
#include <cuda_runtime.h>
#include <cuda_fp16.h>
#include <cstdint>

// ============================================================================
// Sizes
// ============================================================================
#define MDIM 16384
#define NDIM 2048
#define KDIM 2048

#define BM 128
#define BN 256
#define BK 32
#define NK (KDIM / BK)            // 64 k-chunks
#define NTILES (NDIM / BN)        // 8
#define MTILES (MDIM / BM)        // 128
#define GRID_CTAS (MTILES * NTILES)  // 1024

// Static SMEM, 2 stages: per stage A 128x64B = 8192B, B 256x64B = 16384B.
// Stage = 24576B, total = 49152B = 48KB exactly (static limit; NO attribute
// call -- dynamic-smem attribute path kills the harness container).
// Rows are 64B (32 halfs) with XOR swizzle: 16B chunk' = chunk ^ ((row>>1)&3).
// This is conflict-free for the quad-word LDS pattern and preserves
// frag(row+8) = frag(row) + 512B (swizzle term identical for row, row+8).
#define A_TILE_BYTES 8192
#define B_TILE_BYTES 16384
#define STAGE_BYTES  24576
#define SMEM_TOTAL   49152

// ============================================================================
// Static scratch (sanctioned no-alloc path)
// ============================================================================
__device__ __align__(256) __half g_xh[(size_t)MDIM * KDIM];   // 64 MB
__device__ __align__(256) __half g_wh[(size_t)NDIM * KDIM];   // 8 MB

// ============================================================================
// Helpers
// ============================================================================
__device__ __forceinline__ uint32_t smem_u32(const void* p) {
    uint32_t a;
    asm("{ .reg .u64 t; cvta.to.shared.u64 t, %1; cvt.u32.u64 %0, t; }" : "=r"(a) : "l"(p));
    return a;
}

__device__ __forceinline__ void cp_async16(uint32_t dst_smem, const void* src) {
    asm volatile("cp.async.cg.shared.global [%0], [%1], 16;" :: "r"(dst_smem), "l"(src) : "memory");
}
#define CP_COMMIT() asm volatile("cp.async.commit_group;" ::: "memory")
#define CP_WAIT(n)  asm volatile("cp.async.wait_group %0;" :: "n"(n) : "memory")

__device__ __forceinline__ void mma16816(float* d, const uint32_t* a, const uint32_t* b) {
    asm volatile(
        "mma.sync.aligned.m16n8k16.row.col.f32.f16.f16.f32 "
        "{%0,%1,%2,%3}, {%4,%5,%6,%7}, {%8,%9}, {%0,%1,%2,%3};"
        : "+f"(d[0]), "+f"(d[1]), "+f"(d[2]), "+f"(d[3])
        : "r"(a[0]), "r"(a[1]), "r"(a[2]), "r"(a[3]), "r"(b[0]), "r"(b[1]));
}

// swizzled byte offset of a 16B chunk within a 64B-pitch tile
__device__ __forceinline__ int swz_off(int row, int chunk) {
    return row * 64 + ((chunk ^ ((row >> 1) & 3)) << 4);
}

// ============================================================================
// Phase 1a: W_eff = weight + sum_r kron(L0_r,L1_r,L2_r)[:2048,:2048]  -> fp16
// ============================================================================
__global__ void __launch_bounds__(256) prep_w_kernel(const float* __restrict__ weight,
                                                     const float* __restrict__ leaf) {
    int idx = blockIdx.x * 256 + threadIdx.x;   // exactly NDIM*KDIM threads
    int n = idx >> 11;
    int k = idx & 2047;
    int n1 = n / 169; int nr = n - n1 * 169; int n2 = nr / 13; int n3 = nr - n2 * 13;
    int k1 = k / 169; int kr = k - k1 * 169; int k2 = kr / 13; int k3 = kr - k2 * 13;
    float d = 0.f;
#pragma unroll
    for (int r = 0; r < 4; r++) {
        float a = __ldg(&leaf[((0 * 4 + r) * 13 + n1) * 13 + k1]);
        float b = __ldg(&leaf[((1 * 4 + r) * 13 + n2) * 13 + k2]);
        float c = __ldg(&leaf[((2 * 4 + r) * 13 + n3) * 13 + k3]);
        d += a * b * c;
    }
    g_wh[idx] = __float2half(weight[idx] + d);
}

// ============================================================================
// Phase 1b: x fp32 -> fp16
// ============================================================================
__global__ void __launch_bounds__(256) convert_x_kernel(const float4* __restrict__ x) {
    size_t i = (size_t)blockIdx.x * 256 + threadIdx.x;   // M*K/4 threads
    float4 v = x[i];
    __half2 h0 = __floats2half2_rn(v.x, v.y);
    __half2 h1 = __floats2half2_rn(v.z, v.w);
    __half2* p = reinterpret_cast<__half2*>(g_xh);
    p[2 * i] = h0;
    p[2 * i + 1] = h1;
}

// ============================================================================
// Phase 2: GEMM  y = x @ W_eff^T + bias   (fp16 HMMA, fp32 accum)
// CTA 128x256, 8 warps (2x4), warp tile 64x64, BK=32, 2-stage cp.async,
// 48KB static smem, XOR-swizzled 64B rows.
// ============================================================================
__global__ void __launch_bounds__(256, 1)
gemm_kernel(const float* __restrict__ bias, float* __restrict__ out)
{
    __shared__ __align__(16) char smem[SMEM_TOTAL];
    const uint32_t sb = smem_u32(smem);
    const int tid = threadIdx.x;
    const int lane = tid & 31;
    const int wid = tid >> 5;
    const int wm = wid >> 2;           // 0..1  (64-row half)
    const int wn = wid & 3;            // 0..3  (64-col quarter)
    const int r1 = lane >> 2;          // 0..7
    const int c0 = (lane & 3) * 2;     // 0,2,4,6

    const int ntile = (int)blockIdx.x & (NTILES - 1);
    const int mtile = (int)blockIdx.x >> 3;
    const int m0 = mtile * BM;
    const int n0 = ntile * BN;

    const __half* gA = g_xh + (size_t)m0 * KDIM;
    const __half* gB = g_wh + (size_t)n0 * KDIM;

    // ---- async stage loader: A 512 + B 1024 16B chunks, 6 per thread ----
    auto load_stage = [&](int kc, int s) {
        uint32_t sa = sb + s * STAGE_BYTES;
        uint32_t sB = sa + A_TILE_BYTES;
        int koff = kc * BK;
#pragma unroll
        for (int i = 0; i < 2; i++) {
            int c = tid + 256 * i;           // 0..511
            int row = c >> 2, k8 = c & 3;
            cp_async16(sa + swz_off(row, k8), gA + (size_t)row * KDIM + koff + k8 * 8);
        }
#pragma unroll
        for (int i = 0; i < 4; i++) {
            int c = tid + 256 * i;           // 0..1023
            int row = c >> 2, k8 = c & 3;
            cp_async16(sB + swz_off(row, k8), gB + (size_t)row * KDIM + koff + k8 * 8);
        }
        CP_COMMIT();
    };

    float acc[4][8][4];
#pragma unroll
    for (int i = 0; i < 4; i++)
#pragma unroll
        for (int j = 0; j < 8; j++)
#pragma unroll
            for (int q = 0; q < 4; q++) acc[i][j][q] = 0.f;

    load_stage(0, 0);   // prologue

    for (int kc = 0; kc < NK; kc++) {
        if (kc + 1 < NK) {
            load_stage(kc + 1, (kc + 1) & 1);
            CP_WAIT(1);          // stage kc complete (kc+1 still in flight)
        } else {
            CP_WAIT(0);
        }
        __syncthreads();

        const char* sa = smem + (kc & 1) * STAGE_BYTES;
        const char* sB = sa + A_TILE_BYTES;

#pragma unroll
        for (int kk = 0; kk < BK; kk += 16) {
            // fragment byte offsets within a row: a0/b0 at (kk+c0)*2, a2/b1 +16
            const int byte0 = (kk + c0) * 2;       // 0..12 | 32..44
            const int ch0 = byte0 >> 4;            // 0 | 2
            const int w0 = byte0 & 15;

            uint32_t a[4][4];
            uint32_t b[8][2];
#pragma unroll
            for (int ma = 0; ma < 4; ma++) {
                int row = wm * 64 + ma * 16 + r1;
                int s = (row >> 1) & 3;            // same for row and row+8
                int o0 = row * 64 + ((ch0 ^ s) << 4) + w0;
                int o2 = row * 64 + (((ch0 + 1) ^ s) << 4) + w0;
                a[ma][0] = *(const uint32_t*)(sa + o0);
                a[ma][1] = *(const uint32_t*)(sa + o0 + 512);    // +8 rows
                a[ma][2] = *(const uint32_t*)(sa + o2);
                a[ma][3] = *(const uint32_t*)(sa + o2 + 512);
            }
#pragma unroll
            for (int nb = 0; nb < 8; nb++) {
                int row = wn * 64 + nb * 8 + r1;
                int s = (row >> 1) & 3;
                b[nb][0] = *(const uint32_t*)(sB + row * 64 + ((ch0 ^ s) << 4) + w0);
                b[nb][1] = *(const uint32_t*)(sB + row * 64 + (((ch0 + 1) ^ s) << 4) + w0);
            }
#pragma unroll
            for (int ma = 0; ma < 4; ma++)
#pragma unroll
                for (int nb = 0; nb < 8; nb++)
                    mma16816(acc[ma][nb], a[ma], b[nb]);
        }
        __syncthreads();   // all warps done with buffer kc&1 before refill
    }

    // ---- epilogue: + bias, fp32 out ----
#pragma unroll
    for (int ma = 0; ma < 4; ma++) {
        int row0 = m0 + wm * 64 + ma * 16 + r1;
        float* orow0 = out + (size_t)row0 * NDIM;
        float* orow1 = orow0 + (size_t)8 * NDIM;
#pragma unroll
        for (int nb = 0; nb < 8; nb++) {
            int col = n0 + wn * 64 + nb * 8 + c0;
            float bv0 = __ldg(&bias[col]);
            float bv1 = __ldg(&bias[col + 1]);
            float2 v0 = make_float2(acc[ma][nb][0] + bv0, acc[ma][nb][1] + bv1);
            float2 v1 = make_float2(acc[ma][nb][2] + bv0, acc[ma][nb][3] + bv1);
            *reinterpret_cast<float2*>(orow0 + col) = v0;
            *reinterpret_cast<float2*>(orow1 + col) = v1;
        }
    }
}

// ============================================================================
// Host: kernel launches only -- no attribute calls, no allocation, no sync.
// ============================================================================
extern "C" void kernel_launch(void* const* d_in, const int* in_sizes, int n_in,
                              void* d_out, int out_size) {
    // Identify inputs by element count (robust to metadata ordering).
    const float* x = nullptr;
    const float* leaf = nullptr;
    const float* weight = nullptr;
    const float* bias = nullptr;
    for (int i = 0; i < n_in; i++) {
        switch (in_sizes[i]) {
            case 2028:     leaf   = (const float*)d_in[i]; break;  // 3*4*13*13
            case 2048:     bias   = (const float*)d_in[i]; break;
            case 4194304:  weight = (const float*)d_in[i]; break;  // 2048*2048
            default:       x      = (const float*)d_in[i]; break;  // 8*2048*2048
        }
    }
    float* out = (float*)d_out;

    prep_w_kernel<<<(NDIM * KDIM) / 256, 256>>>(weight, leaf);
    convert_x_kernel<<<(int)(((size_t)MDIM * KDIM / 4) / 256), 256>>>((const float4*)x);
    gemm_kernel<<<GRID_CTAS, 256>>>(bias, out);
}